// round 4
// baseline (speedup 1.0000x reference)
#include <cuda_runtime.h>

#define BB   256
#define TT   32
#define ENCD 128
#define DECD 128

typedef unsigned long long ULL;

// Device-global scratch
__device__ float  g_E1[BB * TT * ENCD];   // [B][T][128] = enc @ W1e^T + b1
__device__ float  g_W1P[128 * 256];       // [j][k] W1 hc-part, row-major
__device__ float4 g_Whh4[32 * 512];       // [k4][r] : float4 = Whh[r][4k4..4k4+3]

__device__ __forceinline__ float fast_tanh(float x) {
    float y;
    asm("tanh.approx.f32 %0, %1;" : "=f"(y) : "f"(x));
    return y;
}
__device__ __forceinline__ float fast_sig(float x) {
    return 0.5f + 0.5f * fast_tanh(0.5f * x);
}
__device__ __forceinline__ ULL fma2(ULL a, ULL b, ULL c) {
    ULL d;
    asm("fma.rn.f32x2 %0, %1, %2, %3;" : "=l"(d) : "l"(a), "l"(b), "l"(c));
    return d;
}
__device__ __forceinline__ float2 unpack2(ULL v) {
    float2 r;
    asm("mov.b64 {%0, %1}, %2;" : "=f"(r.x), "=f"(r.y) : "l"(v));
    return r;
}
#define BAR_ATTN() asm volatile("bar.sync 1, 256;" ::: "memory")

// ---------------------------------------------------------------------------
// Prep: E1 (blocks 0..255), Whh repack (256..263), W1 pack (264..271)
// ---------------------------------------------------------------------------
__global__ void __launch_bounds__(128)
prep_kernel(const float* __restrict__ enc,
            const float* __restrict__ W1,    // [128, 384] cols: [hc(256) | enc(128)]
            const float* __restrict__ b1,
            const float* __restrict__ Whh)   // [512,128]
{
    int bid = blockIdx.x;
    if (bid < BB) {
        __shared__ float enc_s[TT * ENCD];
        const float* eb = enc + bid * TT * ENCD;
        for (int i = threadIdx.x; i < TT * ENCD; i += blockDim.x)
            enc_s[i] = eb[i];
        __syncthreads();
        int h = threadIdx.x;
        float acc[TT];
        float bb = b1[h];
#pragma unroll
        for (int t = 0; t < TT; t++) acc[t] = bb;
        const float4* wrow = reinterpret_cast<const float4*>(W1 + h * 384 + 256);
#pragma unroll 2
        for (int k4 = 0; k4 < ENCD / 4; k4++) {
            float4 w = wrow[k4];
#pragma unroll
            for (int t = 0; t < TT; t++) {
                float4 e = reinterpret_cast<const float4*>(enc_s + t * ENCD)[k4];
                acc[t] += w.x * e.x + w.y * e.y + w.z * e.z + w.w * e.w;
            }
        }
        float* outp = g_E1 + bid * TT * ENCD;
#pragma unroll
        for (int t = 0; t < TT; t++) outp[t * ENCD + h] = acc[t];
    } else if (bid < 264) {
        int base = (bid - 256) * 8192;
        float* dst = reinterpret_cast<float*>(g_Whh4);
        for (int i = base + threadIdx.x; i < base + 8192; i += 128) {
            int k4 = i >> 11;
            int r  = (i >> 2) & 511;
            int m  = i & 3;
            dst[i] = Whh[r * 128 + (k4 << 2) + m];
        }
    } else {
        int jbase = (bid - 264) * 16;
        for (int idx = threadIdx.x; idx < 16 * 256; idx += 128) {
            int j = jbase + (idx >> 8), k = idx & 255;
            g_W1P[j * 256 + k] = W1[j * 384 + k];
        }
    }
}

// ---------------------------------------------------------------------------
// Main: 128 blocks x 512 threads, 2 batches/block.
// Warps 0-7: attention chain (A,B,C,D,E). Warps 8-15: gates GEMV (F).
// ---------------------------------------------------------------------------
__global__ void __launch_bounds__(512, 1)
decoder_kernel(const float* __restrict__ enc,
               const float* __restrict__ yhist,
               const float* __restrict__ W2,
               const float* __restrict__ Wih,
               const float* __restrict__ bih,
               const float* __restrict__ bhh,
               const float* __restrict__ fcW,
               const float* __restrict__ fcb,
               const float* __restrict__ fcfW,
               const float* __restrict__ fcfb,
               float* __restrict__ out)
{
    extern __shared__ float sm[];
    float* sE1    = sm;                 // 8192 [g][t][128]
    float* sEnc   = sE1 + 8192;         // 8192 [g][t][128]
    float* sHb    = sEnc + 8192;        // 512  [g][h(0..127) c(128..255)]
    float* sgates = sHb + 512;          // 1024 float2[512]: [r] -> (b0,b1)
    float* sctx2  = sgates + 1024;      // 512  float2[256]: [th][g][64]
    float* sctxC  = sctx2 + 512;        // 256  [g][128] combined ctx
    float* su     = sctxC + 256;        // 256  [g][128]
    float* sWih   = su + 256;           // 512
    float* sbias  = sWih + 512;         // 512
    float* sW2    = sbias + 512;        // 128
    float* sfcf   = sW2 + 128;          // 256
    float* sfc    = sfcf + 256;         // 132 (129 used + fcb at [129])
    float* sAtt2  = sfc + 132;          // 128 float2[64]: (a,a) per (g,t)
    float* slogS  = sAtt2 + 128;        // 64
    float* sY     = slogS + 64;         // 4

    const int tid  = threadIdx.x;
    const int lane = tid & 31;
    const int warp = tid >> 5;
    const int bp   = blockIdx.x * 2;

    // ---- A persistent weights (attn threads; harmless elsewhere) ----
    const int ja = ((warp & 7) << 4) | (lane & 15);   // hidden index 0..127
    const int kh = lane >> 4;                          // k-half of hc (0:h, 1:c)
    ulonglong2 w1r2[16];
    {
        const ulonglong2* src =
            reinterpret_cast<const ulonglong2*>(g_W1P + ja * 256 + kh * 128);
#pragma unroll
        for (int i = 0; i < 16; i++) w1r2[i] = src[i];
    }

    // ---- load phase ----
    for (int i = tid; i < 2048; i += 512) {
        reinterpret_cast<float4*>(sE1)[i] =
            reinterpret_cast<const float4*>(g_E1 + (size_t)bp * TT * ENCD)[i];
        reinterpret_cast<float4*>(sEnc)[i] =
            reinterpret_cast<const float4*>(enc + (size_t)bp * TT * ENCD)[i];
    }
    sWih[tid]  = Wih[tid];
    sbias[tid] = bih[tid] + bhh[tid];
    if (tid < 512) {}
    if (tid < 128) sW2[tid]  = W2[tid];
    if (tid < 256) sfcf[tid] = fcfW[tid];
    if (tid < 130) sfc[tid]  = (tid < 129) ? fcW[tid] : fcb[0];
    if (tid < 512) { sHb[tid] = 0.f; }
    __syncthreads();

    for (int step = 0; step < TT; step++) {
        if (warp < 8) {
            // ======== attention chain (256 threads) ========
            // ---- A: u[g][ja] = hc[g] . W1[ja]  (f32x2 over k-pairs)
            {
                const ulonglong2* h0 =
                    reinterpret_cast<const ulonglong2*>(sHb) + kh * 16;
                const ulonglong2* h1 =
                    reinterpret_cast<const ulonglong2*>(sHb + 256) + kh * 16;
                ULL aA = 0, aB = 0, bA = 0, bB = 0;
#pragma unroll
                for (int i = 0; i < 16; i += 2) {
                    ulonglong2 w  = w1r2[i];
                    ulonglong2 x  = h0[i];
                    ulonglong2 y  = h1[i];
                    aA = fma2(w.x, x.x, aA); aA = fma2(w.y, x.y, aA);
                    bA = fma2(w.x, y.x, bA); bA = fma2(w.y, y.y, bA);
                    ulonglong2 w2 = w1r2[i + 1];
                    ulonglong2 x2 = h0[i + 1];
                    ulonglong2 y2 = h1[i + 1];
                    aB = fma2(w2.x, x2.x, aB); aB = fma2(w2.y, x2.y, aB);
                    bB = fma2(w2.x, y2.x, bB); bB = fma2(w2.y, y2.y, bB);
                }
                float2 pa = unpack2(aA), pb = unpack2(aB);
                float2 qa_ = unpack2(bA), qb = unpack2(bB);
                float s0 = pa.x + pa.y + pb.x + pb.y;
                float s1 = qa_.x + qa_.y + qb.x + qb.y;
                s0 += __shfl_xor_sync(0xffffffffu, s0, 16);
                s1 += __shfl_xor_sync(0xffffffffu, s1, 16);
                if (lane < 16) { su[ja] = s0; su[128 + ja] = s1; }
            }
            BAR_ATTN();

            // ---- B: 64 logits; warp covers 8 rows, 8-lane groups, 2 iters
            {
                int c8 = lane & 7, p2 = lane >> 3;
#pragma unroll
                for (int i = 0; i < 2; i++) {
                    int p  = ((warp & 7) << 3) | (p2 << 1) | i;
                    int pg = p >> 5, pt = p & 31;
                    const float4* e1r = reinterpret_cast<const float4*>(
                        sE1 + (pg * 32 + pt) * 128) + c8 * 4;
                    const float4* ur  = reinterpret_cast<const float4*>(
                        su + pg * 128) + c8 * 4;
                    const float4* wr  = reinterpret_cast<const float4*>(sW2) + c8 * 4;
                    float s = 0.f;
#pragma unroll
                    for (int c = 0; c < 4; c++) {
                        float4 e = e1r[c];
                        float4 u = ur[c];
                        float4 w = wr[c];
                        s += fast_tanh(e.x + u.x) * w.x + fast_tanh(e.y + u.y) * w.y
                           + fast_tanh(e.z + u.z) * w.z + fast_tanh(e.w + u.w) * w.w;
                    }
                    s += __shfl_xor_sync(0xffffffffu, s, 1);
                    s += __shfl_xor_sync(0xffffffffu, s, 2);
                    s += __shfl_xor_sync(0xffffffffu, s, 4);
                    if (c8 == 0) slogS[p] = s;
                }
            }
            BAR_ATTN();

            // ---- C: softmax (warps 0,1 = batch 0,1); write (a,a) packed
            if (warp < 2) {
                float l  = slogS[warp * 32 + lane];
                float mx = l;
#pragma unroll
                for (int o = 16; o > 0; o >>= 1)
                    mx = fmaxf(mx, __shfl_xor_sync(0xffffffffu, mx, o));
                float e   = __expf(l - mx);
                float sum = e;
#pragma unroll
                for (int o = 16; o > 0; o >>= 1)
                    sum += __shfl_xor_sync(0xffffffffu, sum, o);
                float a = e / sum;
                reinterpret_cast<float2*>(sAtt2)[warp * 32 + lane] =
                    make_float2(a, a);
            }
            BAR_ATTN();

            // ---- D: ctx partials, f32x2 over j-pairs, t split 2-way
            {
                int jp = tid & 63, gD = (tid >> 6) & 1, th = (tid >> 7) & 1;
                const ULL* e2 = reinterpret_cast<const ULL*>(sEnc)
                              + gD * 2048 + th * 16 * 64 + jp;
                const ULL* a2 = reinterpret_cast<const ULL*>(sAtt2)
                              + gD * 32 + th * 16;
                ULL acc = 0;
#pragma unroll
                for (int t = 0; t < 16; t++)
                    acc = fma2(a2[t], e2[t * 64], acc);
                float2 c = unpack2(acc);
                reinterpret_cast<float2*>(sctx2)[th * 128 + gD * 64 + jp] = c;
            }
            BAR_ATTN();

            // ---- E: y_tilde (warps 0,1); also store combined ctx
            if (warp < 2) {
                const float2* p0 = reinterpret_cast<const float2*>(sctx2) + warp * 64;
                const float2* p1 = p0 + 128;
                float2 ca = make_float2(p0[lane].x + p1[lane].x,
                                        p0[lane].y + p1[lane].y);
                float2 cb = make_float2(p0[lane + 32].x + p1[lane + 32].x,
                                        p0[lane + 32].y + p1[lane + 32].y);
                reinterpret_cast<float2*>(sctxC)[warp * 64 + lane]      = ca;
                reinterpret_cast<float2*>(sctxC)[warp * 64 + lane + 32] = cb;
                float s = ca.x * sfc[2 * lane] + ca.y * sfc[2 * lane + 1]
                        + cb.x * sfc[64 + 2 * lane] + cb.y * sfc[64 + 2 * lane + 1];
#pragma unroll
                for (int o = 16; o > 0; o >>= 1)
                    s += __shfl_xor_sync(0xffffffffu, s, o);
                if (lane == 0) {
                    float yt = yhist[(bp + warp) * TT + step];
                    sY[warp] = s + yt * sfc[128] + sfc[129];
                }
            }
        } else {
            // ======== F: gates partial = Whh @ h (256 threads) ========
            int ft = tid - 256;            // 0..255
            int r0 = ft, r1 = ft + 256;
            const ulonglong2* h0p = reinterpret_cast<const ulonglong2*>(sHb);
            const ulonglong2* h1p = reinterpret_cast<const ulonglong2*>(sHb + 256);
            ULL a00 = 0, a01 = 0, a10 = 0, a11 = 0;
#pragma unroll
            for (int m = 0; m < 16; m++) {
                ulonglong2 w0 = __ldca(reinterpret_cast<const ulonglong2*>(
                                           g_Whh4 + m * 512 + r0));
                ulonglong2 w1 = __ldca(reinterpret_cast<const ulonglong2*>(
                                           g_Whh4 + m * 512 + r1));
                ulonglong2 hx = h0p[m];
                ulonglong2 hy = h1p[m];
                a00 = fma2(w0.x, hx.x, a00); a00 = fma2(w0.y, hx.y, a00);
                a01 = fma2(w0.x, hy.x, a01); a01 = fma2(w0.y, hy.y, a01);
                a10 = fma2(w1.x, hx.x, a10); a10 = fma2(w1.y, hx.y, a10);
                a11 = fma2(w1.x, hy.x, a11); a11 = fma2(w1.y, hy.y, a11);
            }
#pragma unroll
            for (int m = 16; m < 32; m++) {
                ulonglong2 w0 = __ldcg(reinterpret_cast<const ulonglong2*>(
                                           g_Whh4 + m * 512 + r0));
                ulonglong2 w1 = __ldcg(reinterpret_cast<const ulonglong2*>(
                                           g_Whh4 + m * 512 + r1));
                ulonglong2 hx = h0p[m];
                ulonglong2 hy = h1p[m];
                a00 = fma2(w0.x, hx.x, a00); a00 = fma2(w0.y, hx.y, a00);
                a01 = fma2(w0.x, hy.x, a01); a01 = fma2(w0.y, hy.y, a01);
                a10 = fma2(w1.x, hx.x, a10); a10 = fma2(w1.y, hx.y, a10);
                a11 = fma2(w1.x, hy.x, a11); a11 = fma2(w1.y, hy.y, a11);
            }
            float2 u00 = unpack2(a00), u01 = unpack2(a01);
            float2 u10 = unpack2(a10), u11 = unpack2(a11);
            reinterpret_cast<float2*>(sgates)[r0] =
                make_float2(u00.x + u00.y, u01.x + u01.y);
            reinterpret_cast<float2*>(sgates)[r1] =
                make_float2(u10.x + u10.y, u11.x + u11.y);
        }
        __syncthreads();

        // ---- G: combine + LSTM cell (256 threads)
        if (tid < 256) {
            int j = tid & 127, g = tid >> 7;
            float y = sY[g];
            float gv[4];
#pragma unroll
            for (int q = 0; q < 4; q++) {
                int r = q * 128 + j;
                gv[q] = sgates[r * 2 + g] + sbias[r] + y * sWih[r];
            }
            float c_old = sHb[g * 256 + 128 + j];
            float si = fast_sig(gv[0]);
            float sf = fast_sig(gv[1]);
            float so = fast_sig(gv[3]);
            float cn = sf * c_old + si * fast_tanh(gv[2]);
            float hn = so * fast_tanh(cn);
            sHb[g * 256 + 128 + j] = cn;
            sHb[g * 256 + j]       = hn;
        }
        __syncthreads();
    }

    // ---- final: out[b] = [h, ctx] . fcfW + fcfb + y_history[b, T-1]
    if (warp < 2) {
        float4 hv = reinterpret_cast<const float4*>(sHb + warp * 256)[lane];
        float4 f1 = reinterpret_cast<const float4*>(sfcf)[lane];
        float4 cv = reinterpret_cast<const float4*>(sctxC + warp * 128)[lane];
        float4 f2 = reinterpret_cast<const float4*>(sfcf + 128)[lane];
        float s = hv.x * f1.x + hv.y * f1.y + hv.z * f1.z + hv.w * f1.w
                + cv.x * f2.x + cv.y * f2.y + cv.z * f2.z + cv.w * f2.w;
#pragma unroll
        for (int o = 16; o > 0; o >>= 1)
            s += __shfl_xor_sync(0xffffffffu, s, o);
        if (lane == 0)
            out[bp + warp] = s + fcfb[0] + yhist[(bp + warp) * TT + (TT - 1)];
    }
}

// ---------------------------------------------------------------------------
extern "C" void kernel_launch(void* const* d_in, const int* in_sizes, int n_in,
                              void* d_out, int out_size)
{
    const float* enc  = (const float*)d_in[0];
    const float* yh   = (const float*)d_in[1];
    const float* W1   = (const float*)d_in[2];
    const float* b1   = (const float*)d_in[3];
    const float* W2   = (const float*)d_in[4];
    // d_in[5] = attn_b2 : cancels in softmax
    const float* Wih  = (const float*)d_in[6];
    const float* Whh  = (const float*)d_in[7];
    const float* bih  = (const float*)d_in[8];
    const float* bhh  = (const float*)d_in[9];
    const float* fcW  = (const float*)d_in[10];
    const float* fcb  = (const float*)d_in[11];
    const float* fcfW = (const float*)d_in[12];
    const float* fcfb = (const float*)d_in[13];
    float* out = (float*)d_out;

    const size_t smem_floats = 8192 + 8192 + 512 + 1024 + 512 + 256 + 256
                             + 512 + 512 + 128 + 256 + 132 + 128 + 64 + 4;
    const size_t smem = smem_floats * sizeof(float);   // ~82.7 KB

    cudaFuncSetAttribute(decoder_kernel,
                         cudaFuncAttributeMaxDynamicSharedMemorySize, (int)smem);
    // keep smem carveout small so ~128KB of Whh stays resident in L1D
    cudaFuncSetAttribute(decoder_kernel,
                         cudaFuncAttributePreferredSharedMemoryCarveout, 36);

    prep_kernel<<<272, 128>>>(enc, W1, b1, Whh);
    decoder_kernel<<<128, 512, smem>>>(enc, yh, W2, Wih, bih, bhh,
                                       fcW, fcb, fcfW, fcfb, out);
}